// round 11
// baseline (speedup 1.0000x reference)
#include <cuda_runtime.h>
#include <cuda_bf16.h>
#include <cuda_fp16.h>

// Problem constants: I, J are [B=2, 1, D=192, H=192, W=192] fp32.
#define Bv   2
#define Dv   192
#define Hv   192
#define Wv   192
#define HWv  (Hv * Wv)              // 36864
#define HW2v (HWv / 2)              // 18432 (half2 granules per plane)
#define DHWv (Dv * Hv * Wv)         // 7077888
#define Nv   ((size_t)Bv * DHWv)    // 14155776
#define K_SUM 729.0f

#define HT     16                   // output H rows per p12 block
#define HTILES (Hv / HT)            // 12
#define HROWS  (HT + 8)             // 24 input rows incl. halo

#define DCH    48                   // D-chunk for pass3
#define DCHN   (Dv / DCH)           // 4
#define P3GRID (Bv * (Hv / 2) * DCHN)   // 768

// Intermediates: 5 planar fp16 channels of HW-box-sums + fp16 copies of I, J.
__device__ __align__(16) __half g_bufB[5 * Nv];
__device__ __align__(16) __half g_Ih[Nv];
__device__ __align__(16) __half g_Jh[Nv];
__device__ double g_acc;
__device__ unsigned g_count;        // zero-init; self-resetting

static __device__ __forceinline__ float4 f4z() { return make_float4(0.f, 0.f, 0.f, 0.f); }

static __device__ __forceinline__ void f4acc(float4& a, float4 b) {
    a.x += b.x; a.y += b.y; a.z += b.z; a.w += b.w;
}
static __device__ __forceinline__ void f4dec(float4& a, float4 b) {
    a.x -= b.x; a.y -= b.y; a.z -= b.z; a.w -= b.w;
}

static __device__ __forceinline__ void st_half4(__half* dst, float4 v) {
    __half2 a = __floats2half2_rn(v.x, v.y);
    __half2 b = __floats2half2_rn(v.z, v.w);
    uint2 u;
    u.x = *(unsigned*)&a;
    u.y = *(unsigned*)&b;
    *(uint2*)dst = u;
}

static __device__ __forceinline__ float4 h4f(uint2 u) {
    __half2 a = *(__half2*)&u.x;
    __half2 b = *(__half2*)&u.y;
    float2 fa = __half22float2(a), fb = __half22float2(b);
    return make_float4(fa.x, fa.y, fb.x, fb.y);
}

static __device__ __forceinline__ void f2acc(float2& a, __half2 h) {
    float2 f = __half22float2(h);
    a.x += f.x; a.y += f.y;
}
static __device__ __forceinline__ void f2dec(float2& a, __half2 h) {
    float2 f = __half22float2(h);
    a.x -= f.x; a.y -= f.y;
}

// ---------------------------------------------------------------------------
// Fused pass: products + W box-sum + H box-sum (round-10 version, 62.5us).
// ---------------------------------------------------------------------------
__global__ void __launch_bounds__(192) p12_k(const float* __restrict__ I,
                                             const float* __restrict__ J) {
    extern __shared__ char smraw[];
    __half* wsh = (__half*)smraw;            // [5][HROWS][Wv] fp16

    const int tid  = threadIdx.x;
    const int tile = blockIdx.x % HTILES;
    const int slab = blockIdx.x / HTILES;    // b*Dv + d
    const int h0   = tile * HT;
    const size_t sbase = (size_t)slab * HWv;

    if (blockIdx.x == 0 && tid == 0) g_acc = 0.0;

    // Phase A: 576 units = 24 rows x 24 8-wide segments; 3 per thread.
#pragma unroll
    for (int rep = 0; rep < 3; rep++) {
        const int u    = tid + rep * 192;
        const int r    = u / 24;             // row in tile (0..23)
        const int seg  = u % 24;             // 8-wide W segment
        const int h_in = h0 - 4 + r;
        const bool okh = (h_in >= 0) && (h_in < Hv);
        const size_t rb = sbase + (size_t)h_in * Wv;
        const int wb   = seg * 8 - 4;        // window start (16 floats)

        float fI[16], fJ[16];
#pragma unroll
        for (int j = 0; j < 4; j++) {
            int c0 = wb + 4 * j;
            float4 a = f4z(), bq = f4z();
            if (okh && c0 >= 0 && c0 <= Wv - 4) {
                a  = *(const float4*)(I + rb + c0);
                bq = *(const float4*)(J + rb + c0);
            }
            fI[4*j+0] = a.x;  fI[4*j+1] = a.y;  fI[4*j+2] = a.z;  fI[4*j+3] = a.w;
            fJ[4*j+0] = bq.x; fJ[4*j+1] = bq.y; fJ[4*j+2] = bq.z; fJ[4*j+3] = bq.w;
        }

        // Emit fp16 I,J for pass3 (interior rows; tiles partition H).
        if (okh && h_in >= h0 && h_in < h0 + HT) {
            st_half4(g_Ih + rb + wb + 4, make_float4(fI[4], fI[5], fI[6], fI[7]));
            st_half4(g_Ih + rb + wb + 8, make_float4(fI[8], fI[9], fI[10], fI[11]));
            st_half4(g_Jh + rb + wb + 4, make_float4(fJ[4], fJ[5], fJ[6], fJ[7]));
            st_half4(g_Jh + rb + wb + 8, make_float4(fJ[8], fJ[9], fJ[10], fJ[11]));
        }

#pragma unroll
        for (int ch = 0; ch < 5; ch++) {
            float t[16];
#pragma unroll
            for (int k = 0; k < 16; k++)
                t[k] = (ch == 0) ? fI[k] : (ch == 1) ? fJ[k] :
                       (ch == 2) ? fI[k] * fI[k] : (ch == 3) ? fJ[k] * fJ[k] :
                       fI[k] * fJ[k];
            float S = t[0]+t[1]+t[2]+t[3]+t[4]+t[5]+t[6]+t[7]+t[8];
            float4 oa, ob;
            oa.x = S;
            S += t[9]  - t[0]; oa.y = S;
            S += t[10] - t[1]; oa.z = S;
            S += t[11] - t[2]; oa.w = S;
            S += t[12] - t[3]; ob.x = S;
            S += t[13] - t[4]; ob.y = S;
            S += t[14] - t[5]; ob.z = S;
            S += t[15] - t[6]; ob.w = S;
            __half* wp = wsh + (ch * HROWS + r) * Wv + seg * 8;
            st_half4(wp, oa);
            st_half4(wp + 4, ob);
        }
    }
    __syncthreads();

    // Phase B: 240 (channel, column) units; 9-slot packed register ring.
    int u = tid;
#pragma unroll
    for (int rep = 0; rep < 2; rep++) {
        if (u < 240) {
            const int ch  = u / 48;
            const int col = u % 48;
            const uint2* wsc = (const uint2*)(wsh + ch * HROWS * Wv);
            __half* outp = g_bufB + (size_t)ch * Nv + sbase + (size_t)h0 * Wv + col * 4;

            uint2 ring[9];
            float4 s = f4z();
#pragma unroll
            for (int m = 0; m < 9; m++) {
                ring[m] = wsc[m * 48 + col];
                f4acc(s, h4f(ring[m]));
            }
#pragma unroll
            for (int t = 0; t < 16; t++) {
                st_half4(outp + (size_t)t * Wv, s);
                if (t < 15) {
                    uint2 add = wsc[(t + 9) * 48 + col];
                    f4acc(s, h4f(add));
                    f4dec(s, h4f(ring[t % 9]));
                    ring[t % 9] = add;
                }
            }
        }
        u += 192;
    }
}

// ---------------------------------------------------------------------------
// Pass 3: D box-sum + NCC combine + reduction + fused finalize.
// half2 ownership (2 W-columns/thread): smem ring shrinks to 30.7 KB ->
// ~7 blocks/SM instead of 3, fixing the measured occupancy cap (23%).
// Ring keeps DRAM traffic at the 222 MB minimum (lesson: lag windows
// do NOT survive in L2 under streaming).
// ---------------------------------------------------------------------------
__global__ void __launch_bounds__(192) pass3_k(float* __restrict__ out) {
    extern __shared__ unsigned ring[];       // [5][8][192] half2-as-uint
    __shared__ float red[6];

    const int tid   = threadIdx.x;
    const int lane  = tid % 96;              // half2 column (cols 2lane, 2lane+1)
    const int hrow  = tid / 96;              // 0..1
    const int bid   = blockIdx.x;
    const int chunk = bid % DCHN;
    const int bh2   = bid / DCHN;
    const int b     = bh2 / (Hv / 2);
    const int h     = (bh2 % (Hv / 2)) * 2 + hrow;
    const int d0    = chunk * DCH;

    const size_t base2 = ((size_t)b * DHWv + (size_t)h * Wv) / 2 + lane;

    const __half2* __restrict__ c0 = (const __half2*)g_bufB;
    const __half2* __restrict__ c1 = (const __half2*)(g_bufB + Nv);
    const __half2* __restrict__ c2 = (const __half2*)(g_bufB + 2 * Nv);
    const __half2* __restrict__ c3 = (const __half2*)(g_bufB + 3 * Nv);
    const __half2* __restrict__ c4 = (const __half2*)(g_bufB + 4 * Nv);
    const __half2* __restrict__ Ih = (const __half2*)g_Ih;
    const __half2* __restrict__ Jh = (const __half2*)g_Jh;

#define RING(ch, slot) ring[((ch) * 8 + (slot)) * 192 + tid]
#define U2H(x) (*(__half2*)&(x))
#define H2U(x) (*(unsigned*)&(x))

    float2 s0 = {0.f,0.f}, s1 = {0.f,0.f}, s2 = {0.f,0.f}, s3 = {0.f,0.f}, s4 = {0.f,0.f};
    const __half2 hz = __floats2half2_rn(0.f, 0.f);

#pragma unroll
    for (int m = 0; m < 8; m++) {            // planes d0-4 .. d0+3
        int d = d0 - 4 + m;
        __half2 v0 = hz, v1 = hz, v2 = hz, v3 = hz, v4 = hz;
        if (d >= 0) {
            size_t o = base2 + (size_t)d * HW2v;
            v0 = c0[o]; v1 = c1[o]; v2 = c2[o]; v3 = c3[o]; v4 = c4[o];
        }
        RING(0, m) = H2U(v0); RING(1, m) = H2U(v1); RING(2, m) = H2U(v2);
        RING(3, m) = H2U(v3); RING(4, m) = H2U(v4);
        f2acc(s0, v0); f2acc(s1, v1); f2acc(s2, v2); f2acc(s3, v3); f2acc(s4, v4);
    }

    float local = 0.f;
    const float inv_k = 1.0f / K_SUM;

#pragma unroll 8
    for (int t = 0; t < DCH; t++) {
        int d = d0 + t;
        size_t o = base2 + (size_t)d * HW2v;

        __half2 l0 = hz, l1 = hz, l2 = hz, l3 = hz, l4 = hz;
        if (d + 4 < Dv) {
            size_t ol = o + 4 * (size_t)HW2v;
            l0 = c0[ol]; l1 = c1[ol]; l2 = c2[ol]; l3 = c3[ol]; l4 = c4[ol];
        }
        f2acc(s0, l0); f2acc(s1, l1); f2acc(s2, l2); f2acc(s3, l3); f2acc(s4, l4);

        float2 iv = __half22float2(Ih[o]);
        float2 jv = __half22float2(Jh[o]);

#define COMB(C) { \
        float iu = iv.C * inv_k, ju = jv.C * inv_k; \
        float cross = s4.C - s0.C * ju - s1.C * iu + iu * ju * K_SUM; \
        float ivar  = s2.C - 2.f * s0.C * iu + iu * iu * K_SUM; \
        float jvar  = s3.C - 2.f * s1.C * ju + ju * ju * K_SUM; \
        local += (cross * cross) / (ivar * jvar + 1e-5f); }

        COMB(x) COMB(y)
#undef COMB

        int slot = t & 7;
        unsigned r0 = RING(0, slot), r1 = RING(1, slot), r2 = RING(2, slot);
        unsigned r3 = RING(3, slot), r4 = RING(4, slot);
        f2dec(s0, U2H(r0)); f2dec(s1, U2H(r1)); f2dec(s2, U2H(r2));
        f2dec(s3, U2H(r3)); f2dec(s4, U2H(r4));
        RING(0, slot) = H2U(l0); RING(1, slot) = H2U(l1); RING(2, slot) = H2U(l2);
        RING(3, slot) = H2U(l3); RING(4, slot) = H2U(l4);
    }
#undef RING
#undef U2H
#undef H2U

    // Reduce 192 threads -> 1 double atomic; last block finalizes.
    float v = local;
#pragma unroll
    for (int off = 16; off > 0; off >>= 1)
        v += __shfl_down_sync(0xffffffffu, v, off);
    if ((tid & 31) == 0) red[tid >> 5] = v;
    __syncthreads();
    if (tid == 0) {
        float s = 0.f;
#pragma unroll
        for (int i = 0; i < 6; i++) s += red[i];
        atomicAdd(&g_acc, (double)s);
        __threadfence();
        unsigned done = atomicAdd(&g_count, 1u);
        if (done == (unsigned)(P3GRID - 1)) {
            g_count = 0;                     // self-reset for next replay
            out[0] = (float)(-g_acc / (double)Nv);
        }
    }
}

extern "C" void kernel_launch(void* const* d_in, const int* in_sizes, int n_in,
                              void* d_out, int out_size) {
    const float* I = (const float*)d_in[0];
    const float* J = (const float*)d_in[1];
    float* out = (float*)d_out;

    const int p12_smem = 5 * HROWS * Wv * 2;                  // 46080 B
    const int p3_smem  = 5 * 8 * 192 * (int)sizeof(unsigned); // 30720 B
    cudaFuncSetAttribute(p12_k, cudaFuncAttributeMaxDynamicSharedMemorySize, p12_smem);
    cudaFuncSetAttribute(pass3_k, cudaFuncAttributeMaxDynamicSharedMemorySize, p3_smem);

    p12_k<<<Bv * Dv * HTILES, 192, p12_smem>>>(I, J);         // 4608 blocks
    pass3_k<<<P3GRID, 192, p3_smem>>>(out);                   // 768 blocks
}

// round 12
// speedup vs baseline: 1.7485x; 1.7485x over previous
#include <cuda_runtime.h>
#include <cuda_bf16.h>
#include <cuda_fp16.h>

// Problem constants: I, J are [B=2, 1, D=192, H=192, W=192] fp32.
#define Bv   2
#define Dv   192
#define Hv   192
#define Wv   192
#define HWv  (Hv * Wv)              // 36864
#define HW4v (HWv / 4)              // 9216 (half4 granules per plane)
#define DHWv (Dv * Hv * Wv)         // 7077888
#define Nv   ((size_t)Bv * DHWv)    // 14155776
#define K_SUM 729.0f

#define HT     16                   // output H rows per p12 block
#define HTILES (Hv / HT)            // 12
#define HROWS  (HT + 8)             // 24 input rows incl. halo

#define DCH    32                   // D-chunk for pass3
#define DCHN   (Dv / DCH)           // 6
#define P3T    96                   // pass3 threads per block
#define P3GRID (Bv * (Hv / 2) * DCHN)   // 1152

// Intermediates: 5 planar fp16 channels of HW-box-sums + fp16 copies of I, J.
__device__ __align__(16) __half g_bufB[5 * Nv];
__device__ __align__(16) __half g_Ih[Nv];
__device__ __align__(16) __half g_Jh[Nv];
__device__ double g_acc;
__device__ unsigned g_count;        // zero-init; self-resetting

static __device__ __forceinline__ float4 f4z() { return make_float4(0.f, 0.f, 0.f, 0.f); }

static __device__ __forceinline__ void f4acc(float4& a, float4 b) {
    a.x += b.x; a.y += b.y; a.z += b.z; a.w += b.w;
}
static __device__ __forceinline__ void f4dec(float4& a, float4 b) {
    a.x -= b.x; a.y -= b.y; a.z -= b.z; a.w -= b.w;
}

static __device__ __forceinline__ void st_half4(__half* dst, float4 v) {
    __half2 a = __floats2half2_rn(v.x, v.y);
    __half2 b = __floats2half2_rn(v.z, v.w);
    uint2 u;
    u.x = *(unsigned*)&a;
    u.y = *(unsigned*)&b;
    *(uint2*)dst = u;
}

static __device__ __forceinline__ float4 h4f(uint2 u) {
    __half2 a = *(__half2*)&u.x;
    __half2 b = *(__half2*)&u.y;
    float2 fa = __half22float2(a), fb = __half22float2(b);
    return make_float4(fa.x, fa.y, fb.x, fb.y);
}

// ---------------------------------------------------------------------------
// Fused pass: products + W box-sum + H box-sum (round-10 version, 62.5us).
// ---------------------------------------------------------------------------
__global__ void __launch_bounds__(192) p12_k(const float* __restrict__ I,
                                             const float* __restrict__ J) {
    extern __shared__ char smraw[];
    __half* wsh = (__half*)smraw;            // [5][HROWS][Wv] fp16

    const int tid  = threadIdx.x;
    const int tile = blockIdx.x % HTILES;
    const int slab = blockIdx.x / HTILES;    // b*Dv + d
    const int h0   = tile * HT;
    const size_t sbase = (size_t)slab * HWv;

    if (blockIdx.x == 0 && tid == 0) g_acc = 0.0;

    // Phase A: 576 units = 24 rows x 24 8-wide segments; 3 per thread.
#pragma unroll
    for (int rep = 0; rep < 3; rep++) {
        const int u    = tid + rep * 192;
        const int r    = u / 24;             // row in tile (0..23)
        const int seg  = u % 24;             // 8-wide W segment
        const int h_in = h0 - 4 + r;
        const bool okh = (h_in >= 0) && (h_in < Hv);
        const size_t rb = sbase + (size_t)h_in * Wv;
        const int wb   = seg * 8 - 4;        // window start (16 floats)

        float fI[16], fJ[16];
#pragma unroll
        for (int j = 0; j < 4; j++) {
            int c0 = wb + 4 * j;
            float4 a = f4z(), bq = f4z();
            if (okh && c0 >= 0 && c0 <= Wv - 4) {
                a  = *(const float4*)(I + rb + c0);
                bq = *(const float4*)(J + rb + c0);
            }
            fI[4*j+0] = a.x;  fI[4*j+1] = a.y;  fI[4*j+2] = a.z;  fI[4*j+3] = a.w;
            fJ[4*j+0] = bq.x; fJ[4*j+1] = bq.y; fJ[4*j+2] = bq.z; fJ[4*j+3] = bq.w;
        }

        // Emit fp16 I,J for pass3 (interior rows; tiles partition H).
        if (okh && h_in >= h0 && h_in < h0 + HT) {
            st_half4(g_Ih + rb + wb + 4, make_float4(fI[4], fI[5], fI[6], fI[7]));
            st_half4(g_Ih + rb + wb + 8, make_float4(fI[8], fI[9], fI[10], fI[11]));
            st_half4(g_Jh + rb + wb + 4, make_float4(fJ[4], fJ[5], fJ[6], fJ[7]));
            st_half4(g_Jh + rb + wb + 8, make_float4(fJ[8], fJ[9], fJ[10], fJ[11]));
        }

#pragma unroll
        for (int ch = 0; ch < 5; ch++) {
            float t[16];
#pragma unroll
            for (int k = 0; k < 16; k++)
                t[k] = (ch == 0) ? fI[k] : (ch == 1) ? fJ[k] :
                       (ch == 2) ? fI[k] * fI[k] : (ch == 3) ? fJ[k] * fJ[k] :
                       fI[k] * fJ[k];
            float S = t[0]+t[1]+t[2]+t[3]+t[4]+t[5]+t[6]+t[7]+t[8];
            float4 oa, ob;
            oa.x = S;
            S += t[9]  - t[0]; oa.y = S;
            S += t[10] - t[1]; oa.z = S;
            S += t[11] - t[2]; oa.w = S;
            S += t[12] - t[3]; ob.x = S;
            S += t[13] - t[4]; ob.y = S;
            S += t[14] - t[5]; ob.z = S;
            S += t[15] - t[6]; ob.w = S;
            __half* wp = wsh + (ch * HROWS + r) * Wv + seg * 8;
            st_half4(wp, oa);
            st_half4(wp + 4, ob);
        }
    }
    __syncthreads();

    // Phase B: 240 (channel, column) units; 9-slot packed register ring.
    int u = tid;
#pragma unroll
    for (int rep = 0; rep < 2; rep++) {
        if (u < 240) {
            const int ch  = u / 48;
            const int col = u % 48;
            const uint2* wsc = (const uint2*)(wsh + ch * HROWS * Wv);
            __half* outp = g_bufB + (size_t)ch * Nv + sbase + (size_t)h0 * Wv + col * 4;

            uint2 ring[9];
            float4 s = f4z();
#pragma unroll
            for (int m = 0; m < 9; m++) {
                ring[m] = wsc[m * 48 + col];
                f4acc(s, h4f(ring[m]));
            }
#pragma unroll
            for (int t = 0; t < 16; t++) {
                st_half4(outp + (size_t)t * Wv, s);
                if (t < 15) {
                    uint2 add = wsc[(t + 9) * 48 + col];
                    f4acc(s, h4f(add));
                    f4dec(s, h4f(ring[t % 9]));
                    ring[t % 9] = add;
                }
            }
        }
        u += 192;
    }
}

// ---------------------------------------------------------------------------
// Pass 3 (round-9 inner loop, re-geometried): 96 threads = 48 col-groups x
// 2 h-rows; uint2 (4-column) ownership; smem ring 30.7KB -> 7 blocks/SM.
// DCH=32 -> 1152 blocks so the capacity is used. Fused finalize.
// ---------------------------------------------------------------------------
__global__ void __launch_bounds__(P3T) pass3_k(float* __restrict__ out) {
    extern __shared__ uint2 ring[];          // [5][8][P3T]
    __shared__ float red[3];

    const int tid   = threadIdx.x;
    const int cg    = tid % 48;              // column group (cols 4cg..4cg+3)
    const int hrow  = tid / 48;              // 0..1
    const int bid   = blockIdx.x;
    const int chunk = bid % DCHN;
    const int bh2   = bid / DCHN;
    const int b     = bh2 / (Hv / 2);
    const int h     = (bh2 % (Hv / 2)) * 2 + hrow;
    const int d0    = chunk * DCH;

    const size_t base4 = ((size_t)b * DHWv + (size_t)h * Wv) / 4 + cg;

    const uint2* __restrict__ c0 = (const uint2*)g_bufB;
    const uint2* __restrict__ c1 = (const uint2*)(g_bufB + Nv);
    const uint2* __restrict__ c2 = (const uint2*)(g_bufB + 2 * Nv);
    const uint2* __restrict__ c3 = (const uint2*)(g_bufB + 3 * Nv);
    const uint2* __restrict__ c4 = (const uint2*)(g_bufB + 4 * Nv);
    const uint2* __restrict__ Ih = (const uint2*)g_Ih;
    const uint2* __restrict__ Jh = (const uint2*)g_Jh;

#define RING(ch, slot) ring[((ch) * 8 + (slot)) * P3T + tid]

    float4 s0 = f4z(), s1 = f4z(), s2 = f4z(), s3 = f4z(), s4 = f4z();
    const uint2 uz = make_uint2(0u, 0u);

#pragma unroll
    for (int m = 0; m < 8; m++) {            // planes d0-4 .. d0+3
        int d = d0 - 4 + m;
        uint2 v0 = uz, v1 = uz, v2 = uz, v3 = uz, v4 = uz;
        if (d >= 0) {
            size_t o = base4 + (size_t)d * HW4v;
            v0 = c0[o]; v1 = c1[o]; v2 = c2[o]; v3 = c3[o]; v4 = c4[o];
        }
        RING(0, m) = v0; RING(1, m) = v1; RING(2, m) = v2;
        RING(3, m) = v3; RING(4, m) = v4;
        f4acc(s0, h4f(v0)); f4acc(s1, h4f(v1)); f4acc(s2, h4f(v2));
        f4acc(s3, h4f(v3)); f4acc(s4, h4f(v4));
    }

    float local = 0.f;
    const float inv_k = 1.0f / K_SUM;

#pragma unroll 4
    for (int t = 0; t < DCH; t++) {
        int d = d0 + t;
        size_t o = base4 + (size_t)d * HW4v;

        uint2 l0 = uz, l1 = uz, l2 = uz, l3 = uz, l4 = uz;
        if (d + 4 < Dv) {
            size_t ol = o + 4 * (size_t)HW4v;
            l0 = c0[ol]; l1 = c1[ol]; l2 = c2[ol]; l3 = c3[ol]; l4 = c4[ol];
        }
        f4acc(s0, h4f(l0)); f4acc(s1, h4f(l1)); f4acc(s2, h4f(l2));
        f4acc(s3, h4f(l3)); f4acc(s4, h4f(l4));

        float4 iv = h4f(Ih[o]);
        float4 jv = h4f(Jh[o]);

#define COMB(C) { \
        float iu = iv.C * inv_k, ju = jv.C * inv_k; \
        float cross = s4.C - s0.C * ju - s1.C * iu + iu * ju * K_SUM; \
        float ivar  = s2.C - 2.f * s0.C * iu + iu * iu * K_SUM; \
        float jvar  = s3.C - 2.f * s1.C * ju + ju * ju * K_SUM; \
        local += (cross * cross) / (ivar * jvar + 1e-5f); }

        COMB(x) COMB(y) COMB(z) COMB(w)
#undef COMB

        int slot = t & 7;
        f4dec(s0, h4f(RING(0, slot))); f4dec(s1, h4f(RING(1, slot)));
        f4dec(s2, h4f(RING(2, slot))); f4dec(s3, h4f(RING(3, slot)));
        f4dec(s4, h4f(RING(4, slot)));
        RING(0, slot) = l0; RING(1, slot) = l1; RING(2, slot) = l2;
        RING(3, slot) = l3; RING(4, slot) = l4;
    }
#undef RING

    // Reduce 96 threads (3 warps) -> 1 double atomic; last block finalizes.
    float v = local;
#pragma unroll
    for (int off = 16; off > 0; off >>= 1)
        v += __shfl_down_sync(0xffffffffu, v, off);
    if ((tid & 31) == 0) red[tid >> 5] = v;
    __syncthreads();
    if (tid == 0) {
        float s = red[0] + red[1] + red[2];
        atomicAdd(&g_acc, (double)s);
        __threadfence();
        unsigned done = atomicAdd(&g_count, 1u);
        if (done == (unsigned)(P3GRID - 1)) {
            g_count = 0;                     // self-reset for next replay
            out[0] = (float)(-g_acc / (double)Nv);
        }
    }
}

extern "C" void kernel_launch(void* const* d_in, const int* in_sizes, int n_in,
                              void* d_out, int out_size) {
    const float* I = (const float*)d_in[0];
    const float* J = (const float*)d_in[1];
    float* out = (float*)d_out;

    const int p12_smem = 5 * HROWS * Wv * 2;                  // 46080 B
    const int p3_smem  = 5 * 8 * P3T * (int)sizeof(uint2);    // 30720 B
    cudaFuncSetAttribute(p12_k, cudaFuncAttributeMaxDynamicSharedMemorySize, p12_smem);
    cudaFuncSetAttribute(pass3_k, cudaFuncAttributeMaxDynamicSharedMemorySize, p3_smem);

    p12_k<<<Bv * Dv * HTILES, 192, p12_smem>>>(I, J);         // 4608 blocks
    pass3_k<<<P3GRID, P3T, p3_smem>>>(out);                   // 1152 blocks
}